// round 4
// baseline (speedup 1.0000x reference)
#include <cuda_runtime.h>
#include <cstdint>

#define B_    256
#define T_    1024
#define IN_   3
#define HID_  512
#define RANK_ 4
#define OUT_  3

#define TPB 64    // 2 warps per block; warp w handles batch 2*bid+w
#define BPB 2     // batches per block
#define UPT 16    // hidden units per lane (16*32 = 512) -> 8 f32x2 pairs

typedef unsigned long long u64;

#define C2LOG2E 2.885390081777927f   // 2*log2(e): tanh prescale folded into U', Win', bin'

// Packed f32x2 FMA (ptxas never auto-fuses; must use PTX fma.rn.f32x2).
__device__ __forceinline__ u64 fma2(u64 a, u64 b, u64 c) {
    u64 d;
    asm("fma.rn.f32x2 %0, %1, %2, %3;" : "=l"(d) : "l"(a), "l"(b), "l"(c));
    return d;
}
__device__ __forceinline__ u64 pack2(float lo, float hi) {
    u64 r;
    asm("mov.b64 %0, {%1, %2};" : "=l"(r) : "f"(lo), "f"(hi));
    return r;
}
__device__ __forceinline__ void unpack2(u64 v, float& lo, float& hi) {
    asm("mov.b64 {%0, %1}, %2;" : "=f"(lo), "=f"(hi) : "l"(v));
}
__device__ __forceinline__ float hadd2(u64 v) {
    float lo, hi;
    unpack2(v, lo, hi);
    return lo + hi;
}

// tanh with the 2*log2(e) prescale already folded into the argument:
// given a' = 2*log2(e)*a, tanh(a) = 1 - 2/(2^a' + 1). Saturates correctly at +-inf.
__device__ __forceinline__ float tanh_pre(float ap) {
    float e;
    asm("ex2.approx.f32 %0, %1;" : "=f"(e) : "f"(ap));
    float r;
    asm("rcp.approx.f32 %0, %1;" : "=f"(r) : "f"(e + 1.0f));
    return fmaf(-2.0f, r, 1.0f);
}

__global__ void __launch_bounds__(TPB)
low_rank_rnn_kernel(const float* __restrict__ x,
                    const float* __restrict__ hidden,
                    const float* __restrict__ U,
                    const float* __restrict__ V,
                    const float* __restrict__ Win,
                    const float* __restrict__ bin,
                    const float* __restrict__ Wout,
                    const float* __restrict__ bout,
                    float* __restrict__ out,    // [B,T,OUT]
                    float* __restrict__ hlast,  // [B,HID]
                    float* __restrict__ rout)   // [B,T,HID]
{
    const int tid  = threadIdx.x;
    const int wid  = tid >> 5;
    const int lane = tid & 31;
    const int b    = blockIdx.x * BPB + wid;
    const int j0   = lane * UPT;

    // smem: x for both batches + lane-major packed weights (conflict-free LDS.64)
    __shared__ float xs[BPB][T_ * IN_];          // 24 KB
    __shared__ u64 wiS[IN_][8][32];              // 6 KB  Win' pairs (prescaled)
    __shared__ u64 biS[8][32];                   // 2 KB  bin' pairs (prescaled)
    __shared__ u64 woS[OUT_][8][32];             // 6 KB  Wout pairs

    // ---- cooperative smem init ----
    {
        const float4* xb4 = (const float4*)(x + (size_t)blockIdx.x * BPB * (T_ * IN_));
        float4* xs4 = (float4*)&xs[0][0];
        #pragma unroll 1
        for (int i = tid; i < (BPB * T_ * IN_) / 4; i += TPB) xs4[i] = xb4[i];

        // pairs: pIdx in [0,256): units j=2*pIdx, 2*pIdx+1; lane_t=j>>4, pp=pIdx&7
        #pragma unroll 1
        for (int pIdx = tid; pIdx < HID_ / 2; pIdx += TPB) {
            int j  = 2 * pIdx;
            int lt = j >> 4;
            int pp = pIdx & 7;
            #pragma unroll
            for (int i = 0; i < IN_; i++)
                wiS[i][pp][lt] = pack2(C2LOG2E * Win[j * IN_ + i],
                                       C2LOG2E * Win[(j + 1) * IN_ + i]);
            biS[pp][lt] = pack2(C2LOG2E * bin[j], C2LOG2E * bin[j + 1]);
            #pragma unroll
            for (int o = 0; o < OUT_; o++)
                woS[o][pp][lt] = pack2(Wout[o * HID_ + j], Wout[o * HID_ + j + 1]);
        }
    }

    // ---- per-lane register weights: U' (prescaled) and V ----
    u64 up[RANK_][8], vp[RANK_][8];
    #pragma unroll
    for (int r = 0; r < RANK_; r++)
        #pragma unroll
        for (int pp = 0; pp < 8; pp++) {
            int j = j0 + 2 * pp;
            up[r][pp] = pack2(C2LOG2E * U[r * HID_ + j], C2LOG2E * U[r * HID_ + j + 1]);
            vp[r][pp] = pack2(V[r * HID_ + j], V[r * HID_ + j + 1]);
        }
    const float bo0 = bout[0], bo1 = bout[1], bo2 = bout[2];

    float h[UPT];
    {
        const float4* hb = (const float4*)(hidden + (size_t)b * HID_ + j0);
        #pragma unroll
        for (int q = 0; q < 4; q++) {
            float4 t4 = hb[q];
            h[4 * q + 0] = t4.x; h[4 * q + 1] = t4.y;
            h[4 * q + 2] = t4.z; h[4 * q + 3] = t4.w;
        }
    }

    __syncthreads();   // one-time: smem weights + xs ready

    // ---- initial p = V @ h (warp-local butterfly, all lanes get sums) ----
    float p0, p1, p2, p3;
    {
        u64 acc[RANK_] = {0ull, 0ull, 0ull, 0ull};
        #pragma unroll
        for (int pp = 0; pp < 8; pp++) {
            u64 hp = pack2(h[2 * pp], h[2 * pp + 1]);
            #pragma unroll
            for (int r = 0; r < RANK_; r++) acc[r] = fma2(hp, vp[r][pp], acc[r]);
        }
        float s0 = hadd2(acc[0]), s1 = hadd2(acc[1]);
        float s2 = hadd2(acc[2]), s3 = hadd2(acc[3]);
        #pragma unroll
        for (int off = 16; off > 0; off >>= 1) {
            s0 += __shfl_xor_sync(0xffffffffu, s0, off);
            s1 += __shfl_xor_sync(0xffffffffu, s1, off);
            s2 += __shfl_xor_sync(0xffffffffu, s2, off);
            s3 += __shfl_xor_sync(0xffffffffu, s3, off);
        }
        p0 = s0; p1 = s1; p2 = s2; p3 = s3;
    }

    // ---- iw' for t=0 (prescaled, packed; smem weights, off-chain) ----
    u64 iw[8];
    {
        float xv0 = xs[wid][0], xv1 = xs[wid][1], xv2 = xs[wid][2];
        u64 X0 = pack2(xv0, xv0), X1 = pack2(xv1, xv1), X2 = pack2(xv2, xv2);
        #pragma unroll
        for (int pp = 0; pp < 8; pp++)
            iw[pp] = fma2(X2, wiS[2][pp][lane],
                     fma2(X1, wiS[1][pp][lane],
                     fma2(X0, wiS[0][pp][lane], biS[pp][lane])));
    }

    float* routb = rout + (size_t)b * T_ * HID_;
    float* outb  = out  + (size_t)b * T_ * OUT_;

    #pragma unroll 1
    for (int t = 0; t < T_; t++) {
        // a' = iw' + U'^T p  (packed; both prescaled by 2*log2(e))
        u64 pB0 = pack2(p0, p0), pB1 = pack2(p1, p1);
        u64 pB2 = pack2(p2, p2), pB3 = pack2(p3, p3);

        u64 pa[RANK_] = {0ull, 0ull, 0ull, 0ull};
        u64 qa[OUT_]  = {0ull, 0ull, 0ull};

        #pragma unroll
        for (int pp = 0; pp < 8; pp++) {
            u64 a = fma2(pB3, up[3][pp], fma2(pB2, up[2][pp],
                    fma2(pB1, up[1][pp], fma2(pB0, up[0][pp], iw[pp]))));
            float a0, a1;
            unpack2(a, a0, a1);
            float h0 = tanh_pre(a0);
            float h1 = tanh_pre(a1);
            h[2 * pp]     = h0;
            h[2 * pp + 1] = h1;
            u64 hp = pack2(h0, h1);
            #pragma unroll
            for (int r = 0; r < RANK_; r++) pa[r] = fma2(hp, vp[r][pp], pa[r]);
            #pragma unroll
            for (int o = 0; o < OUT_; o++)  qa[o] = fma2(hp, woS[o][pp][lane], qa[o]);
        }

        // coalesced r_out store (off the dependency chain)
        float* rp = routb + (size_t)t * HID_ + j0;
        *(float4*)(rp + 0)  = make_float4(h[0],  h[1],  h[2],  h[3]);
        *(float4*)(rp + 4)  = make_float4(h[4],  h[5],  h[6],  h[7]);
        *(float4*)(rp + 8)  = make_float4(h[8],  h[9],  h[10], h[11]);
        *(float4*)(rp + 12) = make_float4(h[12], h[13], h[14], h[15]);

        float s0 = hadd2(pa[0]), s1 = hadd2(pa[1]);
        float s2 = hadd2(pa[2]), s3 = hadd2(pa[3]);
        float q0 = hadd2(qa[0]), q1 = hadd2(qa[1]), q2 = hadd2(qa[2]);

        // prefetch next iw' (independent of butterfly results)
        if (t + 1 < T_) {
            float xv0 = xs[wid][3 * (t + 1) + 0];
            float xv1 = xs[wid][3 * (t + 1) + 1];
            float xv2 = xs[wid][3 * (t + 1) + 2];
            u64 X0 = pack2(xv0, xv0), X1 = pack2(xv1, xv1), X2 = pack2(xv2, xv2);
            #pragma unroll
            for (int pp = 0; pp < 8; pp++)
                iw[pp] = fma2(X2, wiS[2][pp][lane],
                         fma2(X1, wiS[1][pp][lane],
                         fma2(X0, wiS[0][pp][lane], biS[pp][lane])));
        }

        // single warp-local butterfly: no bar.sync, no smem round-trip
        #pragma unroll
        for (int off = 16; off > 0; off >>= 1) {
            s0 += __shfl_xor_sync(0xffffffffu, s0, off);
            s1 += __shfl_xor_sync(0xffffffffu, s1, off);
            s2 += __shfl_xor_sync(0xffffffffu, s2, off);
            s3 += __shfl_xor_sync(0xffffffffu, s3, off);
            q0 += __shfl_xor_sync(0xffffffffu, q0, off);
            q1 += __shfl_xor_sync(0xffffffffu, q1, off);
            q2 += __shfl_xor_sync(0xffffffffu, q2, off);
        }
        p0 = s0; p1 = s1; p2 = s2; p3 = s3;

        if (lane == 0) {
            outb[(size_t)t * OUT_ + 0] = q0 + bo0;
            outb[(size_t)t * OUT_ + 1] = q1 + bo1;
            outb[(size_t)t * OUT_ + 2] = q2 + bo2;
        }
    }

    // h_last
    float* hp = hlast + (size_t)b * HID_ + j0;
    *(float4*)(hp + 0)  = make_float4(h[0],  h[1],  h[2],  h[3]);
    *(float4*)(hp + 4)  = make_float4(h[4],  h[5],  h[6],  h[7]);
    *(float4*)(hp + 8)  = make_float4(h[8],  h[9],  h[10], h[11]);
    *(float4*)(hp + 12) = make_float4(h[12], h[13], h[14], h[15]);
}

extern "C" void kernel_launch(void* const* d_in, const int* in_sizes, int n_in,
                              void* d_out, int out_size) {
    const float* x      = (const float*)d_in[0];
    const float* hidden = (const float*)d_in[1];
    const float* U      = (const float*)d_in[2];
    const float* V      = (const float*)d_in[3];
    const float* Win    = (const float*)d_in[4];
    const float* bin    = (const float*)d_in[5];
    const float* Wout   = (const float*)d_in[6];
    const float* bout   = (const float*)d_in[7];

    float* out   = (float*)d_out;                       // [B,T,OUT]
    float* hlast = out   + (size_t)B_ * T_ * OUT_;      // [B,HID]
    float* rout  = hlast + (size_t)B_ * HID_;           // [B,T,HID]

    low_rank_rnn_kernel<<<B_ / BPB, TPB>>>(x, hidden, U, V, Win, bin, Wout, bout,
                                           out, hlast, rout);
}

// round 5
// speedup vs baseline: 1.7172x; 1.7172x over previous
#include <cuda_runtime.h>
#include <cstdint>

#define B_    256
#define T_    1024
#define IN_   3
#define HID_  512
#define RANK_ 4
#define OUT_  3

#define TPB 128   // 4 warps: pair 0 (warps 0,1) -> batch 2*bid, pair 1 (warps 2,3) -> batch 2*bid+1
#define BPB 2
#define UPT 8     // hidden units per thread (64 threads per batch)

typedef unsigned long long u64;

#define C2LOG2E 2.885390081777927f   // 2*log2(e), folded into U', Win', bin'

__device__ __forceinline__ u64 fma2(u64 a, u64 b, u64 c) {
    u64 d;
    asm("fma.rn.f32x2 %0, %1, %2, %3;" : "=l"(d) : "l"(a), "l"(b), "l"(c));
    return d;
}
__device__ __forceinline__ u64 pack2(float lo, float hi) {
    u64 r;
    asm("mov.b64 %0, {%1, %2};" : "=l"(r) : "f"(lo), "f"(hi));
    return r;
}
__device__ __forceinline__ void unpack2(u64 v, float& lo, float& hi) {
    asm("mov.b64 {%0, %1}, %2;" : "=f"(lo), "=f"(hi) : "l"(v));
}
__device__ __forceinline__ float hadd2(u64 v) {
    float lo, hi;
    unpack2(v, lo, hi);
    return lo + hi;
}

// tanh with 2*log2(e) prescale folded into argument: tanh(a) = 1 - 2/(2^{a'}+1).
// Saturates correctly at +-inf; abs err ~1e-7.
__device__ __forceinline__ float tanh_pre(float ap) {
    float e;
    asm("ex2.approx.f32 %0, %1;" : "=f"(e) : "f"(ap));
    float r;
    asm("rcp.approx.f32 %0, %1;" : "=f"(r) : "f"(e + 1.0f));
    return fmaf(-2.0f, r, 1.0f);
}

__device__ __forceinline__ void bar_pair(int pair) {
    asm volatile("bar.sync %0, 64;" :: "r"(pair + 1) : "memory");
}

__global__ void __launch_bounds__(TPB)
low_rank_rnn_kernel(const float* __restrict__ x,
                    const float* __restrict__ hidden,
                    const float* __restrict__ U,
                    const float* __restrict__ V,
                    const float* __restrict__ Win,
                    const float* __restrict__ bin,
                    const float* __restrict__ Wout,
                    const float* __restrict__ bout,
                    float* __restrict__ out,    // [B,T,OUT]
                    float* __restrict__ hlast,  // [B,HID]
                    float* __restrict__ rout)   // [B,T,HID]
{
    const int tid  = threadIdx.x;
    const int wid  = tid >> 5;
    const int lane = tid & 31;
    const int pair = wid >> 1;       // which batch within the block
    const int wsub = wid & 1;        // warp within the pair
    const int b    = blockIdx.x * BPB + pair;
    const int tp   = wsub * 32 + lane;   // 0..63 within the pair
    const int j0   = tp * UPT;

    __shared__ float xs[BPB][T_ * IN_];                  // 24 KB
    __shared__ __align__(16) float red[BPB][2][8][8];    // per-pair ping-pong

    const bool writer = (lane & 7) == 0;
    const int  wslot  = wsub * 4 + (lane >> 3);

    // ---- stage x for both batches (block-cooperative, vectorized) ----
    {
        const float4* xb4 = (const float4*)(x + (size_t)blockIdx.x * BPB * (T_ * IN_));
        float4* xs4 = (float4*)&xs[0][0];
        #pragma unroll 1
        for (int i = tid; i < (BPB * T_ * IN_) / 4; i += TPB) xs4[i] = xb4[i];
    }

    // ---- per-thread weights, packed over unit pairs (U', Win', bin' prescaled) ----
    u64 up[RANK_][4], vp[RANK_][4], wop[OUT_][4], wip[IN_][4], bip[4];
    #pragma unroll
    for (int r = 0; r < RANK_; r++)
        #pragma unroll
        for (int pp = 0; pp < 4; pp++) {
            int j = j0 + 2 * pp;
            up[r][pp] = pack2(C2LOG2E * U[r * HID_ + j], C2LOG2E * U[r * HID_ + j + 1]);
            vp[r][pp] = pack2(V[r * HID_ + j], V[r * HID_ + j + 1]);
        }
    #pragma unroll
    for (int o = 0; o < OUT_; o++)
        #pragma unroll
        for (int pp = 0; pp < 4; pp++) {
            int j = j0 + 2 * pp;
            wop[o][pp] = pack2(Wout[o * HID_ + j], Wout[o * HID_ + j + 1]);
        }
    #pragma unroll
    for (int i = 0; i < IN_; i++)
        #pragma unroll
        for (int pp = 0; pp < 4; pp++) {
            int j = j0 + 2 * pp;
            wip[i][pp] = pack2(C2LOG2E * Win[j * IN_ + i], C2LOG2E * Win[(j + 1) * IN_ + i]);
        }
    #pragma unroll
    for (int pp = 0; pp < 4; pp++) {
        int j = j0 + 2 * pp;
        bip[pp] = pack2(C2LOG2E * bin[j], C2LOG2E * bin[j + 1]);
    }

    float bo0 = 0.f, bo1 = 0.f, bo2 = 0.f;
    if (tp == 0) { bo0 = bout[0]; bo1 = bout[1]; bo2 = bout[2]; }

    float h[UPT];
    #pragma unroll
    for (int k = 0; k < UPT; k++) h[k] = hidden[(size_t)b * HID_ + j0 + k];

    __syncthreads();   // xs staged (block-wide, one time)

    // ---- initial p = V @ h (into red[pair][1]; t=0 uses red[pair][0]) ----
    {
        u64 acc[RANK_] = {0ull, 0ull, 0ull, 0ull};
        #pragma unroll
        for (int pp = 0; pp < 4; pp++) {
            u64 hp = pack2(h[2 * pp], h[2 * pp + 1]);
            #pragma unroll
            for (int r = 0; r < RANK_; r++) acc[r] = fma2(hp, vp[r][pp], acc[r]);
        }
        float s0 = hadd2(acc[0]), s1 = hadd2(acc[1]);
        float s2 = hadd2(acc[2]), s3 = hadd2(acc[3]);
        #pragma unroll
        for (int off = 1; off <= 4; off <<= 1) {
            s0 += __shfl_xor_sync(0xffffffffu, s0, off);
            s1 += __shfl_xor_sync(0xffffffffu, s1, off);
            s2 += __shfl_xor_sync(0xffffffffu, s2, off);
            s3 += __shfl_xor_sync(0xffffffffu, s3, off);
        }
        if (writer)
            *(float4*)&red[pair][1][wslot][0] = make_float4(s0, s1, s2, s3);
    }
    bar_pair(pair);

    float p0, p1, p2, p3;
    {
        float4 c0 = *(const float4*)&red[pair][1][0][0];
        float4 c1 = *(const float4*)&red[pair][1][1][0];
        float4 c2 = *(const float4*)&red[pair][1][2][0];
        float4 c3 = *(const float4*)&red[pair][1][3][0];
        float4 c4 = *(const float4*)&red[pair][1][4][0];
        float4 c5 = *(const float4*)&red[pair][1][5][0];
        float4 c6 = *(const float4*)&red[pair][1][6][0];
        float4 c7 = *(const float4*)&red[pair][1][7][0];
        p0 = ((c0.x + c1.x) + (c2.x + c3.x)) + ((c4.x + c5.x) + (c6.x + c7.x));
        p1 = ((c0.y + c1.y) + (c2.y + c3.y)) + ((c4.y + c5.y) + (c6.y + c7.y));
        p2 = ((c0.z + c1.z) + (c2.z + c3.z)) + ((c4.z + c5.z) + (c6.z + c7.z));
        p3 = ((c0.w + c1.w) + (c2.w + c3.w)) + ((c4.w + c5.w) + (c6.w + c7.w));
    }

    // ---- iw' for t=0 (prescaled, packed) ----
    u64 iw[4];
    {
        float xv0 = xs[pair][0], xv1 = xs[pair][1], xv2 = xs[pair][2];
        u64 X0 = pack2(xv0, xv0), X1 = pack2(xv1, xv1), X2 = pack2(xv2, xv2);
        #pragma unroll
        for (int pp = 0; pp < 4; pp++)
            iw[pp] = fma2(X2, wip[2][pp], fma2(X1, wip[1][pp], fma2(X0, wip[0][pp], bip[pp])));
    }

    float* routb = rout + (size_t)b * T_ * HID_;
    float* outb  = out  + (size_t)b * T_ * OUT_;

    #pragma unroll 1
    for (int t = 0; t < T_; t++) {
        const int pb = t & 1;

        // a' = iw' + U'^T p (packed, prescaled)
        u64 pB0 = pack2(p0, p0), pB1 = pack2(p1, p1);
        u64 pB2 = pack2(p2, p2), pB3 = pack2(p3, p3);

        u64 pa[RANK_] = {0ull, 0ull, 0ull, 0ull};
        u64 qa[OUT_]  = {0ull, 0ull, 0ull};

        #pragma unroll
        for (int pp = 0; pp < 4; pp++) {
            u64 a = fma2(pB3, up[3][pp], fma2(pB2, up[2][pp],
                    fma2(pB1, up[1][pp], fma2(pB0, up[0][pp], iw[pp]))));
            float a0, a1;
            unpack2(a, a0, a1);
            float h0 = tanh_pre(a0);
            float h1 = tanh_pre(a1);
            h[2 * pp]     = h0;
            h[2 * pp + 1] = h1;
            u64 hp = pack2(h0, h1);
            #pragma unroll
            for (int r = 0; r < RANK_; r++) pa[r] = fma2(hp, vp[r][pp], pa[r]);
            #pragma unroll
            for (int o = 0; o < OUT_; o++)  qa[o] = fma2(hp, wop[o][pp], qa[o]);
        }

        // coalesced r_out store (off the dependency chain)
        *(float4*)(routb + (size_t)t * HID_ + j0)     = make_float4(h[0], h[1], h[2], h[3]);
        *(float4*)(routb + (size_t)t * HID_ + j0 + 4) = make_float4(h[4], h[5], h[6], h[7]);

        float s0 = hadd2(pa[0]), s1 = hadd2(pa[1]);
        float s2 = hadd2(pa[2]), s3 = hadd2(pa[3]);
        float q0 = hadd2(qa[0]), q1 = hadd2(qa[1]), q2 = hadd2(qa[2]);

        // 3-level butterfly (groups of 8 lanes)
        #pragma unroll
        for (int off = 1; off <= 4; off <<= 1) {
            s0 += __shfl_xor_sync(0xffffffffu, s0, off);
            s1 += __shfl_xor_sync(0xffffffffu, s1, off);
            s2 += __shfl_xor_sync(0xffffffffu, s2, off);
            s3 += __shfl_xor_sync(0xffffffffu, s3, off);
            q0 += __shfl_xor_sync(0xffffffffu, q0, off);
            q1 += __shfl_xor_sync(0xffffffffu, q1, off);
            q2 += __shfl_xor_sync(0xffffffffu, q2, off);
        }
        if (writer) {
            *(float4*)&red[pair][pb][wslot][0] = make_float4(s0, s1, s2, s3);
            *(float4*)&red[pair][pb][wslot][4] = make_float4(q0, q1, q2, 0.f);
        }

        // prefetch next iw' in the barrier shadow
        if (t + 1 < T_) {
            float xv0 = xs[pair][3 * (t + 1) + 0];
            float xv1 = xs[pair][3 * (t + 1) + 1];
            float xv2 = xs[pair][3 * (t + 1) + 2];
            u64 X0 = pack2(xv0, xv0), X1 = pack2(xv1, xv1), X2 = pack2(xv2, xv2);
            #pragma unroll
            for (int pp = 0; pp < 4; pp++)
                iw[pp] = fma2(X2, wip[2][pp], fma2(X1, wip[1][pp], fma2(X0, wip[0][pp], bip[pp])));
        }

        bar_pair(pair);   // per-batch named barrier: the two batches never couple

        float4 c0 = *(const float4*)&red[pair][pb][0][0];
        float4 c1 = *(const float4*)&red[pair][pb][1][0];
        float4 c2 = *(const float4*)&red[pair][pb][2][0];
        float4 c3 = *(const float4*)&red[pair][pb][3][0];
        float4 c4 = *(const float4*)&red[pair][pb][4][0];
        float4 c5 = *(const float4*)&red[pair][pb][5][0];
        float4 c6 = *(const float4*)&red[pair][pb][6][0];
        float4 c7 = *(const float4*)&red[pair][pb][7][0];
        p0 = ((c0.x + c1.x) + (c2.x + c3.x)) + ((c4.x + c5.x) + (c6.x + c7.x));
        p1 = ((c0.y + c1.y) + (c2.y + c3.y)) + ((c4.y + c5.y) + (c6.y + c7.y));
        p2 = ((c0.z + c1.z) + (c2.z + c3.z)) + ((c4.z + c5.z) + (c6.z + c7.z));
        p3 = ((c0.w + c1.w) + (c2.w + c3.w)) + ((c4.w + c5.w) + (c6.w + c7.w));

        if (tp == 0) {
            float4 d0 = *(const float4*)&red[pair][pb][0][4];
            float4 d1 = *(const float4*)&red[pair][pb][1][4];
            float4 d2 = *(const float4*)&red[pair][pb][2][4];
            float4 d3 = *(const float4*)&red[pair][pb][3][4];
            float4 d4 = *(const float4*)&red[pair][pb][4][4];
            float4 d5 = *(const float4*)&red[pair][pb][5][4];
            float4 d6 = *(const float4*)&red[pair][pb][6][4];
            float4 d7 = *(const float4*)&red[pair][pb][7][4];
            float o0 = ((d0.x + d1.x) + (d2.x + d3.x)) + ((d4.x + d5.x) + (d6.x + d7.x)) + bo0;
            float o1 = ((d0.y + d1.y) + (d2.y + d3.y)) + ((d4.y + d5.y) + (d6.y + d7.y)) + bo1;
            float o2 = ((d0.z + d1.z) + (d2.z + d3.z)) + ((d4.z + d5.z) + (d6.z + d7.z)) + bo2;
            outb[(size_t)t * OUT_ + 0] = o0;
            outb[(size_t)t * OUT_ + 1] = o1;
            outb[(size_t)t * OUT_ + 2] = o2;
        }
    }

    // h_last
    *(float4*)(hlast + (size_t)b * HID_ + j0)     = make_float4(h[0], h[1], h[2], h[3]);
    *(float4*)(hlast + (size_t)b * HID_ + j0 + 4) = make_float4(h[4], h[5], h[6], h[7]);
}

extern "C" void kernel_launch(void* const* d_in, const int* in_sizes, int n_in,
                              void* d_out, int out_size) {
    const float* x      = (const float*)d_in[0];
    const float* hidden = (const float*)d_in[1];
    const float* U      = (const float*)d_in[2];
    const float* V      = (const float*)d_in[3];
    const float* Win    = (const float*)d_in[4];
    const float* bin    = (const float*)d_in[5];
    const float* Wout   = (const float*)d_in[6];
    const float* bout   = (const float*)d_in[7];

    float* out   = (float*)d_out;                       // [B,T,OUT]
    float* hlast = out   + (size_t)B_ * T_ * OUT_;      // [B,HID]
    float* rout  = hlast + (size_t)B_ * HID_;           // [B,T,HID]

    low_rank_rnn_kernel<<<B_ / BPB, TPB>>>(x, hidden, U, V, Win, bin, Wout, bout,
                                           out, hlast, rout);
}